// round 1
// baseline (speedup 1.0000x reference)
#include <cuda_runtime.h>
#include <cuda_bf16.h>
#include <cstddef>
#include <math.h>

// Problem dims
#define BB 2
#define HH 16
#define TT 2048
#define DD 2048
#define HD 128
#define KK 2048          // reduction dim of projections
#define MM 4096          // B*T rows
#define SCALE 0.08838834764831845f  // 1/sqrt(128)

// ---------------- scratch (device globals; allocation is forbidden) ----------
__device__ float g_q[BB * HH * TT * HD];    // [B,H,T,HD]
__device__ float g_k[BB * HH * TT * HD];    // [B,H,S,HD]
__device__ float g_v[BB * HH * TT * HD];    // [B,H,S,HD]
__device__ float g_ctx[BB * TT * DD];       // [B,T,H,HD] == [B,T,D]

// =============================================================================
// Projection GEMM: out[m, n] = sum_k A[m,k] * W[n,k]   (A: [4096,2048], W: [2048,2048])
// 128x128 tile, BK=16, 256 threads, 8x8 microtile (split 4+4 at +64 offsets).
// ROPE: apply rotary to interleaved pairs in epilogue (cols within head).
// SPLIT: scatter to [B,H,T,HD] (head == blockIdx.x since N-tile == HD == 128).
// =============================================================================
template<bool ROPE, bool SPLIT>
__global__ __launch_bounds__(256)
void proj_kernel(const float* __restrict__ A, const float* __restrict__ W,
                 float* __restrict__ out,
                 const float* __restrict__ cosT, const float* __restrict__ sinT)
{
    __shared__ float As[16][132];
    __shared__ float Bs[16][132];

    const int tid = threadIdx.x;
    const int tx  = tid & 15;      // N direction
    const int ty  = tid >> 4;      // M direction
    const int m0  = blockIdx.y * 128;
    const int n0  = blockIdx.x * 128;

    const int lr = tid >> 2;               // 0..63 (load row)
    const int kq = (tid & 3) * 4;          // 0,4,8,12 (load k offset)

    const float* Ap0 = A + (size_t)(m0 + lr) * KK + kq;
    const float* Ap1 = Ap0 + (size_t)64 * KK;
    const float* Wp0 = W + (size_t)(n0 + lr) * KK + kq;
    const float* Wp1 = Wp0 + (size_t)64 * KK;

    float acc[8][8];
    #pragma unroll
    for (int i = 0; i < 8; i++)
        #pragma unroll
        for (int j = 0; j < 8; j++) acc[i][j] = 0.0f;

    for (int k0 = 0; k0 < KK; k0 += 16) {
        float4 a0 = *(const float4*)(Ap0 + k0);
        float4 a1 = *(const float4*)(Ap1 + k0);
        float4 b0 = *(const float4*)(Wp0 + k0);
        float4 b1 = *(const float4*)(Wp1 + k0);

        __syncthreads();
        As[kq + 0][lr] = a0.x; As[kq + 1][lr] = a0.y;
        As[kq + 2][lr] = a0.z; As[kq + 3][lr] = a0.w;
        As[kq + 0][lr + 64] = a1.x; As[kq + 1][lr + 64] = a1.y;
        As[kq + 2][lr + 64] = a1.z; As[kq + 3][lr + 64] = a1.w;
        Bs[kq + 0][lr] = b0.x; Bs[kq + 1][lr] = b0.y;
        Bs[kq + 2][lr] = b0.z; Bs[kq + 3][lr] = b0.w;
        Bs[kq + 0][lr + 64] = b1.x; Bs[kq + 1][lr + 64] = b1.y;
        Bs[kq + 2][lr + 64] = b1.z; Bs[kq + 3][lr + 64] = b1.w;
        __syncthreads();

        #pragma unroll
        for (int kk = 0; kk < 16; kk++) {
            float4 av0 = *(const float4*)&As[kk][ty * 4];
            float4 av1 = *(const float4*)&As[kk][ty * 4 + 64];
            float4 bv0 = *(const float4*)&Bs[kk][tx * 4];
            float4 bv1 = *(const float4*)&Bs[kk][tx * 4 + 64];
            float af[8] = {av0.x, av0.y, av0.z, av0.w, av1.x, av1.y, av1.z, av1.w};
            float bf[8] = {bv0.x, bv0.y, bv0.z, bv0.w, bv1.x, bv1.y, bv1.z, bv1.w};
            #pragma unroll
            for (int i = 0; i < 8; i++)
                #pragma unroll
                for (int j = 0; j < 8; j++)
                    acc[i][j] = fmaf(af[i], bf[j], acc[i][j]);
        }
    }

    // Epilogue
    #pragma unroll
    for (int ig = 0; ig < 2; ig++) {
        #pragma unroll
        for (int ii = 0; ii < 4; ii++) {
            const int m = m0 + ig * 64 + ty * 4 + ii;
            const int t = m & (TT - 1);
            const int b = m >> 11;
            #pragma unroll
            for (int jg = 0; jg < 2; jg++) {
                const int cl = jg * 64 + tx * 4;   // local col within 128-wide tile
                float v0 = acc[ig * 4 + ii][jg * 4 + 0];
                float v1 = acc[ig * 4 + ii][jg * 4 + 1];
                float v2 = acc[ig * 4 + ii][jg * 4 + 2];
                float v3 = acc[ig * 4 + ii][jg * 4 + 3];
                if (ROPE) {
                    const int d2 = cl >> 1;        // pair index (cl is even)
                    float cs0 = cosT[t * 64 + d2];
                    float sn0 = sinT[t * 64 + d2];
                    float cs1 = cosT[t * 64 + d2 + 1];
                    float sn1 = sinT[t * 64 + d2 + 1];
                    float o0 = v0 * cs0 - v1 * sn0;
                    float o1 = v1 * cs0 + v0 * sn0;
                    float o2 = v2 * cs1 - v3 * sn1;
                    float o3 = v3 * cs1 + v2 * sn1;
                    v0 = o0; v1 = o1; v2 = o2; v3 = o3;
                }
                float* outp;
                if (SPLIT) {
                    const int h = blockIdx.x;      // N-tile == head
                    outp = out + ((((size_t)(b * HH + h)) * TT + t) * HD + cl);
                } else {
                    outp = out + ((size_t)m * DD + n0 + cl);
                }
                *(float4*)outp = make_float4(v0, v1, v2, v3);
            }
        }
    }
}

// =============================================================================
// Flash attention: per (b,h), BR=64 query rows per CTA, BC=64 key chunk.
// smem: Qs[64][132], KVs[64][132] (K then V reuse), Ps[64][68].
// Thread map (256 thr): ty=tid/16 owns rows ty*4..+3; scores cols tx+16j;
// output d-cols tx*4 and tx*4+64.
// =============================================================================
#define QS_STRIDE 132
#define PS_STRIDE 68
#define ATTN_SMEM ((2 * 64 * QS_STRIDE + 64 * PS_STRIDE) * 4)

__global__ __launch_bounds__(256, 2)
void attn_kernel(const float* __restrict__ Q, const float* __restrict__ K,
                 const float* __restrict__ V, float* __restrict__ ctx)
{
    extern __shared__ float sm[];
    float* Qs  = sm;
    float* KVs = sm + 64 * QS_STRIDE;
    float* Ps  = sm + 2 * 64 * QS_STRIDE;

    const int tid = threadIdx.x;
    const int tx  = tid & 15;
    const int ty  = tid >> 4;
    const int bh  = blockIdx.y;
    const int b   = bh >> 4;
    const int h   = bh & 15;

    const float* qb = Q + ((size_t)bh * TT + blockIdx.x * 64) * HD;
    const float* kb = K + (size_t)bh * TT * HD;
    const float* vb = V + (size_t)bh * TT * HD;

    // Load Q block [64][128]
    for (int i = tid; i < 64 * 32; i += 256) {
        const int r = i >> 5;
        const int cq = (i & 31) * 4;
        *(float4*)(Qs + r * QS_STRIDE + cq) = *(const float4*)(qb + r * HD + cq);
    }

    float m_r[4], l_r[4], O[4][8];
    #pragma unroll
    for (int i = 0; i < 4; i++) {
        m_r[i] = -1e30f; l_r[i] = 0.0f;
        #pragma unroll
        for (int j = 0; j < 8; j++) O[i][j] = 0.0f;
    }

    for (int s0 = 0; s0 < TT; s0 += 64) {
        __syncthreads();   // prior PV reads of KVs / Ps done
        // Load K chunk
        for (int i = tid; i < 64 * 32; i += 256) {
            const int r = i >> 5;
            const int cq = (i & 31) * 4;
            *(float4*)(KVs + r * QS_STRIDE + cq) =
                *(const float4*)(kb + (size_t)(s0 + r) * HD + cq);
        }
        __syncthreads();

        // Scores s[i][j] = q_row(ty*4+i) . k_row(tx+16j)
        float s[4][4];
        #pragma unroll
        for (int i = 0; i < 4; i++)
            #pragma unroll
            for (int j = 0; j < 4; j++) s[i][j] = 0.0f;

        for (int d = 0; d < HD; d += 4) {
            float4 qv[4], kv[4];
            #pragma unroll
            for (int i = 0; i < 4; i++)
                qv[i] = *(const float4*)(Qs + (ty * 4 + i) * QS_STRIDE + d);
            #pragma unroll
            for (int j = 0; j < 4; j++)
                kv[j] = *(const float4*)(KVs + (tx + 16 * j) * QS_STRIDE + d);
            #pragma unroll
            for (int i = 0; i < 4; i++)
                #pragma unroll
                for (int j = 0; j < 4; j++) {
                    s[i][j] = fmaf(qv[i].x, kv[j].x, s[i][j]);
                    s[i][j] = fmaf(qv[i].y, kv[j].y, s[i][j]);
                    s[i][j] = fmaf(qv[i].z, kv[j].z, s[i][j]);
                    s[i][j] = fmaf(qv[i].w, kv[j].w, s[i][j]);
                }
        }

        // Online softmax update
        float mc[4], corr[4], ls[4];
        #pragma unroll
        for (int i = 0; i < 4; i++) {
            #pragma unroll
            for (int j = 0; j < 4; j++) s[i][j] *= SCALE;
            mc[i] = fmaxf(fmaxf(s[i][0], s[i][1]), fmaxf(s[i][2], s[i][3]));
            #pragma unroll
            for (int off = 8; off >= 1; off >>= 1)
                mc[i] = fmaxf(mc[i], __shfl_xor_sync(0xffffffffu, mc[i], off));
            const float mnew = fmaxf(m_r[i], mc[i]);
            corr[i] = __expf(m_r[i] - mnew);
            m_r[i] = mnew;
            ls[i] = 0.0f;
            #pragma unroll
            for (int j = 0; j < 4; j++) {
                s[i][j] = __expf(s[i][j] - mnew);
                ls[i] += s[i][j];
            }
            #pragma unroll
            for (int off = 8; off >= 1; off >>= 1)
                ls[i] += __shfl_xor_sync(0xffffffffu, ls[i], off);
            l_r[i] = l_r[i] * corr[i] + ls[i];
            #pragma unroll
            for (int j = 0; j < 8; j++) O[i][j] *= corr[i];
        }

        __syncthreads();   // scores done reading KVs

        // Write P to smem; load V chunk into KVs
        #pragma unroll
        for (int i = 0; i < 4; i++)
            #pragma unroll
            for (int j = 0; j < 4; j++)
                Ps[(ty * 4 + i) * PS_STRIDE + tx + 16 * j] = s[i][j];
        for (int i = tid; i < 64 * 32; i += 256) {
            const int r = i >> 5;
            const int cq = (i & 31) * 4;
            *(float4*)(KVs + r * QS_STRIDE + cq) =
                *(const float4*)(vb + (size_t)(s0 + r) * HD + cq);
        }
        __syncthreads();

        // O += P @ V
        for (int c0 = 0; c0 < 64; c0 += 4) {
            float4 pv[4];
            #pragma unroll
            for (int i = 0; i < 4; i++)
                pv[i] = *(const float4*)(Ps + (ty * 4 + i) * PS_STRIDE + c0);
            #pragma unroll
            for (int cc = 0; cc < 4; cc++) {
                const float* vrow = KVs + (c0 + cc) * QS_STRIDE;
                float4 va = *(const float4*)(vrow + tx * 4);
                float4 vb4 = *(const float4*)(vrow + tx * 4 + 64);
                #pragma unroll
                for (int i = 0; i < 4; i++) {
                    const float p = (cc == 0) ? pv[i].x : (cc == 1) ? pv[i].y
                                  : (cc == 2) ? pv[i].z : pv[i].w;
                    O[i][0] = fmaf(p, va.x, O[i][0]);
                    O[i][1] = fmaf(p, va.y, O[i][1]);
                    O[i][2] = fmaf(p, va.z, O[i][2]);
                    O[i][3] = fmaf(p, va.w, O[i][3]);
                    O[i][4] = fmaf(p, vb4.x, O[i][4]);
                    O[i][5] = fmaf(p, vb4.y, O[i][5]);
                    O[i][6] = fmaf(p, vb4.z, O[i][6]);
                    O[i][7] = fmaf(p, vb4.w, O[i][7]);
                }
            }
        }
    }

    // Epilogue: ctx[b][t][h][hd]
    #pragma unroll
    for (int i = 0; i < 4; i++) {
        const float inv_l = 1.0f / l_r[i];
        const int t = blockIdx.x * 64 + ty * 4 + i;
        float* op = ctx + (((size_t)b * TT + t) * HH + h) * HD;
        *(float4*)(op + tx * 4) =
            make_float4(O[i][0] * inv_l, O[i][1] * inv_l, O[i][2] * inv_l, O[i][3] * inv_l);
        *(float4*)(op + tx * 4 + 64) =
            make_float4(O[i][4] * inv_l, O[i][5] * inv_l, O[i][6] * inv_l, O[i][7] * inv_l);
    }
}

// =============================================================================
extern "C" void kernel_launch(void* const* d_in, const int* in_sizes, int n_in,
                              void* d_out, int out_size)
{
    const float* hs  = (const float*)d_in[0];
    const float* enc = (const float*)d_in[1];
    const float* Wq  = (const float*)d_in[2];
    const float* Wk  = (const float*)d_in[3];
    const float* Wv  = (const float*)d_in[4];
    const float* Wo  = (const float*)d_in[5];
    const float* cq  = (const float*)d_in[6];
    const float* sq  = (const float*)d_in[7];
    const float* ck  = (const float*)d_in[8];
    const float* sk  = (const float*)d_in[9];

    float *q, *k, *v, *ctx;
    cudaGetSymbolAddress((void**)&q,   g_q);
    cudaGetSymbolAddress((void**)&k,   g_k);
    cudaGetSymbolAddress((void**)&v,   g_v);
    cudaGetSymbolAddress((void**)&ctx, g_ctx);

    const dim3 pgrid(DD / 128, MM / 128);   // (16, 32)

    proj_kernel<true,  true ><<<pgrid, 256>>>(hs,  Wq, q,   cq, sq);
    proj_kernel<true,  true ><<<pgrid, 256>>>(enc, Wk, k,   ck, sk);
    proj_kernel<false, true ><<<pgrid, 256>>>(enc, Wv, v,   nullptr, nullptr);

    cudaFuncSetAttribute(attn_kernel,
                         cudaFuncAttributeMaxDynamicSharedMemorySize, ATTN_SMEM);
    attn_kernel<<<dim3(TT / 64, BB * HH), 256, ATTN_SMEM>>>(q, k, v, ctx);

    proj_kernel<false, false><<<pgrid, 256>>>(ctx, Wo, (float*)d_out, nullptr, nullptr);
}

// round 3
// speedup vs baseline: 1.3924x; 1.3924x over previous
#include <cuda_runtime.h>
#include <cuda_bf16.h>
#include <cstdint>
#include <cstddef>
#include <math.h>

// ---------------------------------------------------------------------------
// Problem dims
// ---------------------------------------------------------------------------
#define BB 2
#define HH 16
#define TT 2048
#define DD 2048
#define HD 128
#define KK 2048
#define MM 4096
#define SCALE 0.08838834764831845f

// ---------------------------------------------------------------------------
// Scratch (device globals; allocation is forbidden)
// ---------------------------------------------------------------------------
#define CH (BB * HH * TT * HD)
__device__ float g_qkv[3 * CH];                 // q,k,v fp32 [B,H,T,HD]
__device__ float g_ctx[BB * TT * DD];           // [B,T,H*HD]
__device__ __nv_bfloat16 g_hs_h[MM * KK],  g_hs_l[MM * KK];
__device__ __nv_bfloat16 g_enc_h[MM * KK], g_enc_l[MM * KK];
__device__ __nv_bfloat16 g_ctx_h[MM * KK], g_ctx_l[MM * KK];
__device__ __nv_bfloat16 g_wq_h[DD * KK], g_wq_l[DD * KK];
__device__ __nv_bfloat16 g_wk_h[DD * KK], g_wk_l[DD * KK];
__device__ __nv_bfloat16 g_wv_h[DD * KK], g_wv_l[DD * KK];
__device__ __nv_bfloat16 g_wo_h[DD * KK], g_wo_l[DD * KK];

// ---------------------------------------------------------------------------
// Small PTX helpers (all baseline sm_80/sm_90 features; NO 'a'-gated instrs)
// ---------------------------------------------------------------------------
__device__ __forceinline__ uint32_t smem_to_u32(const void* p) {
    uint32_t a;
    asm("{ .reg .u64 t; cvta.to.shared.u64 t, %1; cvt.u32.u64 %0, t; }" : "=r"(a) : "l"(p));
    return a;
}
__device__ __forceinline__ void cp_async16(uint32_t dst, const void* src) {
    asm volatile("cp.async.cg.shared.global [%0], [%1], 16;" :: "r"(dst), "l"(src));
}
#define CP_ASYNC_COMMIT() asm volatile("cp.async.commit_group;" ::: "memory")
#define CP_ASYNC_WAIT(n)  asm volatile("cp.async.wait_group %0;" :: "n"(n) : "memory")

__device__ __forceinline__ uint32_t lds32(uint32_t a) {
    uint32_t v;
    asm volatile("ld.shared.b32 %0, [%1];" : "=r"(v) : "r"(a));
    return v;
}
__device__ __forceinline__ void mma16816(float* c, const uint32_t* a, uint32_t b0, uint32_t b1) {
    asm volatile("mma.sync.aligned.m16n8k16.row.col.f32.bf16.bf16.f32 "
                 "{%0,%1,%2,%3}, {%4,%5,%6,%7}, {%8,%9}, {%0,%1,%2,%3};"
                 : "+f"(c[0]), "+f"(c[1]), "+f"(c[2]), "+f"(c[3])
                 : "r"(a[0]), "r"(a[1]), "r"(a[2]), "r"(a[3]), "r"(b0), "r"(b1));
}

// ---------------------------------------------------------------------------
// fp32 -> bf16 hi/lo split
// ---------------------------------------------------------------------------
__global__ void split_kernel(const float* __restrict__ x,
                             __nv_bfloat16* __restrict__ hi,
                             __nv_bfloat16* __restrict__ lo, int n4)
{
    int i = blockIdx.x * 256 + threadIdx.x;
    if (i >= n4) return;
    float4 v = ((const float4*)x)[i];
    __nv_bfloat16 h0 = __float2bfloat16(v.x);
    __nv_bfloat16 h1 = __float2bfloat16(v.y);
    __nv_bfloat16 h2 = __float2bfloat16(v.z);
    __nv_bfloat16 h3 = __float2bfloat16(v.w);
    __nv_bfloat16 l0 = __float2bfloat16(v.x - __bfloat162float(h0));
    __nv_bfloat16 l1 = __float2bfloat16(v.y - __bfloat162float(h1));
    __nv_bfloat16 l2 = __float2bfloat16(v.z - __bfloat162float(h2));
    __nv_bfloat16 l3 = __float2bfloat16(v.w - __bfloat162float(h3));
    ((__nv_bfloat162*)hi)[2 * i]     = __nv_bfloat162(h0, h1);
    ((__nv_bfloat162*)hi)[2 * i + 1] = __nv_bfloat162(h2, h3);
    ((__nv_bfloat162*)lo)[2 * i]     = __nv_bfloat162(l0, l1);
    ((__nv_bfloat162*)lo)[2 * i + 1] = __nv_bfloat162(l2, l3);
}

// ---------------------------------------------------------------------------
// bf16x3 GEMM via mma.sync: out[m,n] = sum_k A[m,k]*W[n,k]
// CTA tile 128x128, BK=32, 256 thr (8 warps, 4m x 2n), warp tile 32x64.
// smem per stage: Ah,Al,Wh,Wl each 128 rows x 80B (64B data + swizzle pad).
// ---------------------------------------------------------------------------
#define TILE_B 10240                   // 128 * 80
#define STAGE_B (4 * TILE_B)           // 40960
#define SMEM_GEMM (2 * STAGE_B)        // 81920
#define NSTAGES (KK / 32)              // 64

// byte address of bf16 element (row r, element e) inside a tile
__device__ __forceinline__ uint32_t tile_addr(uint32_t base, int r, int e) {
    int c = (e * 2) >> 4;                       // 16B chunk
    return base + r * 80 + (((c ^ ((r >> 1) & 3)) << 4) | ((e * 2) & 15));
}

__device__ __forceinline__ void load_stage_g(
    uint32_t sbuf, int s, int m0, int n0,
    const __nv_bfloat16* __restrict__ Ah, const __nv_bfloat16* __restrict__ Al,
    const __nv_bfloat16* __restrict__ Wh, const __nv_bfloat16* __restrict__ Wl, int tid)
{
    const int k0 = s * 32;
    #pragma unroll
    for (int half = 0; half < 2; ++half) {
        const int id = tid + 256 * half;        // 0..511
        const int r = id >> 2, c = id & 3;
        const uint32_t doff = r * 80 + ((c ^ ((r >> 1) & 3)) << 4);
        const size_t gA = (size_t)(m0 + r) * KK + k0 + c * 8;
        const size_t gW = (size_t)(n0 + r) * KK + k0 + c * 8;
        cp_async16(sbuf + doff,              Ah + gA);
        cp_async16(sbuf + TILE_B + doff,     Al + gA);
        cp_async16(sbuf + 2 * TILE_B + doff, Wh + gW);
        cp_async16(sbuf + 3 * TILE_B + doff, Wl + gW);
    }
}

template<bool QKV>
__global__ __launch_bounds__(256, 1)
void gemm_kernel(const __nv_bfloat16* __restrict__ hs_h, const __nv_bfloat16* __restrict__ hs_l,
                 const __nv_bfloat16* __restrict__ enc_h, const __nv_bfloat16* __restrict__ enc_l,
                 const __nv_bfloat16* __restrict__ wq_h, const __nv_bfloat16* __restrict__ wq_l,
                 const __nv_bfloat16* __restrict__ wk_h, const __nv_bfloat16* __restrict__ wk_l,
                 const __nv_bfloat16* __restrict__ wv_h, const __nv_bfloat16* __restrict__ wv_l,
                 const float* __restrict__ cq, const float* __restrict__ sq,
                 const float* __restrict__ ck, const float* __restrict__ sk,
                 float* __restrict__ out)
{
    extern __shared__ __align__(128) uint8_t smem_raw[];
    const uint32_t sbase = smem_to_u32(smem_raw);
    const int tid = threadIdx.x;
    const int m0 = blockIdx.y * 128;
    const int n0 = blockIdx.x * 128;
    const int z  = QKV ? blockIdx.z : 0;

    const __nv_bfloat16 *Ah, *Al, *Wh, *Wl;
    if (QKV) {
        Ah = (z == 0) ? hs_h : enc_h;
        Al = (z == 0) ? hs_l : enc_l;
        Wh = (z == 0) ? wq_h : (z == 1) ? wk_h : wv_h;
        Wl = (z == 0) ? wq_l : (z == 1) ? wk_l : wv_l;
    } else {
        Ah = hs_h; Al = hs_l; Wh = wq_h; Wl = wq_l;
    }

    const int wid = tid >> 5, lid = tid & 31;
    const int wm = wid >> 1, wn = wid & 1;      // warp grid 4m x 2n
    const int g = lid >> 2, t = lid & 3;

    float acc[2][8][4];
    #pragma unroll
    for (int mt = 0; mt < 2; ++mt)
        #pragma unroll
        for (int nt = 0; nt < 8; ++nt)
            #pragma unroll
            for (int q = 0; q < 4; ++q) acc[mt][nt][q] = 0.0f;

    load_stage_g(sbase, 0, m0, n0, Ah, Al, Wh, Wl, tid);
    CP_ASYNC_COMMIT();

    for (int s = 0; s < NSTAGES; ++s) {
        if (s + 1 < NSTAGES) {
            load_stage_g(sbase + ((s + 1) & 1) * STAGE_B, s + 1, m0, n0, Ah, Al, Wh, Wl, tid);
            CP_ASYNC_COMMIT();
            CP_ASYNC_WAIT(1);
        } else {
            CP_ASYNC_WAIT(0);
        }
        __syncthreads();

        const uint32_t buf = sbase + (s & 1) * STAGE_B;
        const uint32_t aH = buf, aL = buf + TILE_B;
        const uint32_t bH = buf + 2 * TILE_B, bL = buf + 3 * TILE_B;

        #pragma unroll
        for (int kh = 0; kh < 2; ++kh) {        // two k16 steps in BK=32
            const int e0 = kh * 16 + 2 * t;     // k element for frag regs 0/1
            uint32_t ah[2][4], al[2][4];
            #pragma unroll
            for (int mt = 0; mt < 2; ++mt) {
                const int r0 = wm * 32 + mt * 16 + g;
                ah[mt][0] = lds32(tile_addr(aH, r0,     e0));
                ah[mt][1] = lds32(tile_addr(aH, r0 + 8, e0));
                ah[mt][2] = lds32(tile_addr(aH, r0,     e0 + 8));
                ah[mt][3] = lds32(tile_addr(aH, r0 + 8, e0 + 8));
                al[mt][0] = lds32(tile_addr(aL, r0,     e0));
                al[mt][1] = lds32(tile_addr(aL, r0 + 8, e0));
                al[mt][2] = lds32(tile_addr(aL, r0,     e0 + 8));
                al[mt][3] = lds32(tile_addr(aL, r0 + 8, e0 + 8));
            }
            #pragma unroll
            for (int nt = 0; nt < 8; ++nt) {
                const int rn = wn * 64 + nt * 8 + g;
                const uint32_t bh0 = lds32(tile_addr(bH, rn, e0));
                const uint32_t bh1 = lds32(tile_addr(bH, rn, e0 + 8));
                const uint32_t bl0 = lds32(tile_addr(bL, rn, e0));
                const uint32_t bl1 = lds32(tile_addr(bL, rn, e0 + 8));
                #pragma unroll
                for (int mt = 0; mt < 2; ++mt) {
                    mma16816(acc[mt][nt], ah[mt], bh0, bh1);
                    mma16816(acc[mt][nt], ah[mt], bl0, bl1);
                    mma16816(acc[mt][nt], al[mt], bh0, bh1);
                }
            }
        }
        __syncthreads();
    }

    // ---------------- epilogue ----------------
    // acc[mt][nt]: c0=C[g][2t], c1=C[g][2t+1], c2=C[g+8][2t], c3=C[g+8][2t+1]
    #pragma unroll
    for (int mt = 0; mt < 2; ++mt) {
        #pragma unroll
        for (int rh = 0; rh < 2; ++rh) {
            const int m = m0 + wm * 32 + mt * 16 + g + rh * 8;
            const int tI = m & (TT - 1);
            const int b  = m >> 11;
            #pragma unroll
            for (int nt = 0; nt < 8; ++nt) {
                const int col = wn * 64 + nt * 8 + 2 * t;   // even, 0..126
                float v0 = acc[mt][nt][rh * 2 + 0];
                float v1 = acc[mt][nt][rh * 2 + 1];
                if (QKV) {
                    if (z < 2) {
                        const float* cT = (z == 0) ? cq : ck;
                        const float* sT = (z == 0) ? sq : sk;
                        const int d2 = col >> 1;
                        const float cs = cT[tI * 64 + d2];
                        const float sn = sT[tI * 64 + d2];
                        const float x0 = v0, x1 = v1;
                        v0 = x0 * cs - x1 * sn;
                        v1 = x1 * cs + x0 * sn;
                    }
                    const int h = blockIdx.x;   // N-tile == head (128 cols)
                    float* op = out + (size_t)z * CH +
                                ((((size_t)b * HH + h) * TT + tI) * HD + col);
                    *(float2*)op = make_float2(v0, v1);
                } else {
                    float* op = out + (size_t)m * DD + n0 + col;
                    *(float2*)op = make_float2(v0, v1);
                }
            }
        }
    }
}

// ---------------------------------------------------------------------------
// Flash attention (fp32 SIMT, unchanged — next round's target)
// ---------------------------------------------------------------------------
#define QS_STRIDE 132
#define PS_STRIDE 68
#define ATTN_SMEM ((2 * 64 * QS_STRIDE + 64 * PS_STRIDE) * 4)

__global__ __launch_bounds__(256, 2)
void attn_kernel(const float* __restrict__ Q, const float* __restrict__ K,
                 const float* __restrict__ V, float* __restrict__ ctx)
{
    extern __shared__ float sm[];
    float* Qs  = sm;
    float* KVs = sm + 64 * QS_STRIDE;
    float* Ps  = sm + 2 * 64 * QS_STRIDE;

    const int tid = threadIdx.x;
    const int tx  = tid & 15;
    const int ty  = tid >> 4;
    const int bh  = blockIdx.y;
    const int b   = bh >> 4;
    const int h   = bh & 15;

    const float* qb = Q + ((size_t)bh * TT + blockIdx.x * 64) * HD;
    const float* kb = K + (size_t)bh * TT * HD;
    const float* vb = V + (size_t)bh * TT * HD;

    for (int i = tid; i < 64 * 32; i += 256) {
        const int r = i >> 5;
        const int cq = (i & 31) * 4;
        *(float4*)(Qs + r * QS_STRIDE + cq) = *(const float4*)(qb + r * HD + cq);
    }

    float m_r[4], l_r[4], O[4][8];
    #pragma unroll
    for (int i = 0; i < 4; i++) {
        m_r[i] = -1e30f; l_r[i] = 0.0f;
        #pragma unroll
        for (int j = 0; j < 8; j++) O[i][j] = 0.0f;
    }

    for (int s0 = 0; s0 < TT; s0 += 64) {
        __syncthreads();
        for (int i = tid; i < 64 * 32; i += 256) {
            const int r = i >> 5;
            const int cq = (i & 31) * 4;
            *(float4*)(KVs + r * QS_STRIDE + cq) =
                *(const float4*)(kb + (size_t)(s0 + r) * HD + cq);
        }
        __syncthreads();

        float s[4][4];
        #pragma unroll
        for (int i = 0; i < 4; i++)
            #pragma unroll
            for (int j = 0; j < 4; j++) s[i][j] = 0.0f;

        for (int d = 0; d < HD; d += 4) {
            float4 qv[4], kv[4];
            #pragma unroll
            for (int i = 0; i < 4; i++)
                qv[i] = *(const float4*)(Qs + (ty * 4 + i) * QS_STRIDE + d);
            #pragma unroll
            for (int j = 0; j < 4; j++)
                kv[j] = *(const float4*)(KVs + (tx + 16 * j) * QS_STRIDE + d);
            #pragma unroll
            for (int i = 0; i < 4; i++)
                #pragma unroll
                for (int j = 0; j < 4; j++) {
                    s[i][j] = fmaf(qv[i].x, kv[j].x, s[i][j]);
                    s[i][j] = fmaf(qv[i].y, kv[j].y, s[i][j]);
                    s[i][j] = fmaf(qv[i].z, kv[j].z, s[i][j]);
                    s[i][j] = fmaf(qv[i].w, kv[j].w, s[i][j]);
                }
        }

        float mc[4], corr[4], ls[4];
        #pragma unroll
        for (int i = 0; i < 4; i++) {
            #pragma unroll
            for (int j = 0; j < 4; j++) s[i][j] *= SCALE;
            mc[i] = fmaxf(fmaxf(s[i][0], s[i][1]), fmaxf(s[i][2], s[i][3]));
            #pragma unroll
            for (int off = 8; off >= 1; off >>= 1)
                mc[i] = fmaxf(mc[i], __shfl_xor_sync(0xffffffffu, mc[i], off));
            const float mnew = fmaxf(m_r[i], mc[i]);
            corr[i] = __expf(m_r[i] - mnew);
            m_r[i] = mnew;
            ls[i] = 0.0f;
            #pragma unroll
            for (int j = 0; j < 4; j++) {
                s[i][j] = __expf(s[i][j] - mnew);
                ls[i] += s[i][j];
            }
            #pragma unroll
            for (int off = 8; off >= 1; off >>= 1)
                ls[i] += __shfl_xor_sync(0xffffffffu, ls[i], off);
            l_r[i] = l_r[i] * corr[i] + ls[i];
            #pragma unroll
            for (int j = 0; j < 8; j++) O[i][j] *= corr[i];
        }

        __syncthreads();

        #pragma unroll
        for (int i = 0; i < 4; i++)
            #pragma unroll
            for (int j = 0; j < 4; j++)
                Ps[(ty * 4 + i) * PS_STRIDE + tx + 16 * j] = s[i][j];
        for (int i = tid; i < 64 * 32; i += 256) {
            const int r = i >> 5;
            const int cq = (i & 31) * 4;
            *(float4*)(KVs + r * QS_STRIDE + cq) =
                *(const float4*)(vb + (size_t)(s0 + r) * HD + cq);
        }
        __syncthreads();

        for (int c0 = 0; c0 < 64; c0 += 4) {
            float4 pv[4];
            #pragma unroll
            for (int i = 0; i < 4; i++)
                pv[i] = *(const float4*)(Ps + (ty * 4 + i) * PS_STRIDE + c0);
            #pragma unroll
            for (int cc = 0; cc < 4; cc++) {
                const float* vrow = KVs + (c0 + cc) * QS_STRIDE;
                float4 va  = *(const float4*)(vrow + tx * 4);
                float4 vb4 = *(const float4*)(vrow + tx * 4 + 64);
                #pragma unroll
                for (int i = 0; i < 4; i++) {
                    const float p = (cc == 0) ? pv[i].x : (cc == 1) ? pv[i].y
                                  : (cc == 2) ? pv[i].z : pv[i].w;
                    O[i][0] = fmaf(p, va.x, O[i][0]);
                    O[i][1] = fmaf(p, va.y, O[i][1]);
                    O[i][2] = fmaf(p, va.z, O[i][2]);
                    O[i][3] = fmaf(p, va.w, O[i][3]);
                    O[i][4] = fmaf(p, vb4.x, O[i][4]);
                    O[i][5] = fmaf(p, vb4.y, O[i][5]);
                    O[i][6] = fmaf(p, vb4.z, O[i][6]);
                    O[i][7] = fmaf(p, vb4.w, O[i][7]);
                }
            }
        }
    }

    #pragma unroll
    for (int i = 0; i < 4; i++) {
        const float inv_l = 1.0f / l_r[i];
        const int t = blockIdx.x * 64 + ty * 4 + i;
        float* op = ctx + (((size_t)b * TT + t) * HH + h) * HD;
        *(float4*)(op + tx * 4) =
            make_float4(O[i][0] * inv_l, O[i][1] * inv_l, O[i][2] * inv_l, O[i][3] * inv_l);
        *(float4*)(op + tx * 4 + 64) =
            make_float4(O[i][4] * inv_l, O[i][5] * inv_l, O[i][6] * inv_l, O[i][7] * inv_l);
    }
}

// ---------------------------------------------------------------------------
extern "C" void kernel_launch(void* const* d_in, const int* in_sizes, int n_in,
                              void* d_out, int out_size)
{
    const float* hs  = (const float*)d_in[0];
    const float* enc = (const float*)d_in[1];
    const float* Wq  = (const float*)d_in[2];
    const float* Wk  = (const float*)d_in[3];
    const float* Wv  = (const float*)d_in[4];
    const float* Wo  = (const float*)d_in[5];
    const float* cq  = (const float*)d_in[6];
    const float* sq  = (const float*)d_in[7];
    const float* ck  = (const float*)d_in[8];
    const float* sk  = (const float*)d_in[9];

    float *qkv, *ctx;
    __nv_bfloat16 *hs_h, *hs_l, *enc_h, *enc_l, *ctx_h, *ctx_l;
    __nv_bfloat16 *wq_h, *wq_l, *wk_h, *wk_l, *wv_h, *wv_l, *wo_h, *wo_l;
    cudaGetSymbolAddress((void**)&qkv,   g_qkv);
    cudaGetSymbolAddress((void**)&ctx,   g_ctx);
    cudaGetSymbolAddress((void**)&hs_h,  g_hs_h);  cudaGetSymbolAddress((void**)&hs_l,  g_hs_l);
    cudaGetSymbolAddress((void**)&enc_h, g_enc_h); cudaGetSymbolAddress((void**)&enc_l, g_enc_l);
    cudaGetSymbolAddress((void**)&ctx_h, g_ctx_h); cudaGetSymbolAddress((void**)&ctx_l, g_ctx_l);
    cudaGetSymbolAddress((void**)&wq_h,  g_wq_h);  cudaGetSymbolAddress((void**)&wq_l,  g_wq_l);
    cudaGetSymbolAddress((void**)&wk_h,  g_wk_h);  cudaGetSymbolAddress((void**)&wk_l,  g_wk_l);
    cudaGetSymbolAddress((void**)&wv_h,  g_wv_h);  cudaGetSymbolAddress((void**)&wv_l,  g_wv_l);
    cudaGetSymbolAddress((void**)&wo_h,  g_wo_h);  cudaGetSymbolAddress((void**)&wo_l,  g_wo_l);

    const int nA4 = MM * KK / 4, nW4 = DD * KK / 4;
    split_kernel<<<(nA4 + 255) / 256, 256>>>(hs,  hs_h,  hs_l,  nA4);
    split_kernel<<<(nA4 + 255) / 256, 256>>>(enc, enc_h, enc_l, nA4);
    split_kernel<<<(nW4 + 255) / 256, 256>>>(Wq,  wq_h,  wq_l,  nW4);
    split_kernel<<<(nW4 + 255) / 256, 256>>>(Wk,  wk_h,  wk_l,  nW4);
    split_kernel<<<(nW4 + 255) / 256, 256>>>(Wv,  wv_h,  wv_l,  nW4);
    split_kernel<<<(nW4 + 255) / 256, 256>>>(Wo,  wo_h,  wo_l,  nW4);

    cudaFuncSetAttribute(gemm_kernel<true>,
                         cudaFuncAttributeMaxDynamicSharedMemorySize, SMEM_GEMM);
    cudaFuncSetAttribute(gemm_kernel<false>,
                         cudaFuncAttributeMaxDynamicSharedMemorySize, SMEM_GEMM);

    // Q/K/V projections (+RoPE, +head split) in one launch
    gemm_kernel<true><<<dim3(DD / 128, MM / 128, 3), 256, SMEM_GEMM>>>(
        hs_h, hs_l, enc_h, enc_l, wq_h, wq_l, wk_h, wk_l, wv_h, wv_l,
        cq, sq, ck, sk, qkv);

    cudaFuncSetAttribute(attn_kernel,
                         cudaFuncAttributeMaxDynamicSharedMemorySize, ATTN_SMEM);
    attn_kernel<<<dim3(TT / 64, BB * HH), 256, ATTN_SMEM>>>(
        qkv, qkv + CH, qkv + 2 * CH, ctx);

    // Output projection
    split_kernel<<<(nA4 + 255) / 256, 256>>>(ctx, ctx_h, ctx_l, nA4);
    gemm_kernel<false><<<dim3(DD / 128, MM / 128, 1), 256, SMEM_GEMM>>>(
        ctx_h, ctx_l, nullptr, nullptr, wo_h, wo_l, nullptr, nullptr, nullptr, nullptr,
        nullptr, nullptr, nullptr, nullptr, (float*)d_out);
}

// round 4
// speedup vs baseline: 2.3411x; 1.6813x over previous
#include <cuda_runtime.h>
#include <cuda_bf16.h>
#include <cstdint>
#include <cstddef>
#include <math.h>

// ---------------------------------------------------------------------------
#define BB 2
#define HH 16
#define TT 2048
#define DD 2048
#define HD 128
#define KK 2048
#define MM 4096
#define SCALE 0.08838834764831845f
#define CH (BB * HH * TT * HD)

// ---------------------------------------------------------------------------
// Scratch (device globals; allocation is forbidden)
// ---------------------------------------------------------------------------
__device__ __nv_bfloat16 g_hs_h[MM * KK],  g_hs_l[MM * KK];
__device__ __nv_bfloat16 g_enc_h[MM * KK], g_enc_l[MM * KK];
__device__ __nv_bfloat16 g_wq_h[DD * KK], g_wq_l[DD * KK];
__device__ __nv_bfloat16 g_wk_h[DD * KK], g_wk_l[DD * KK];
__device__ __nv_bfloat16 g_wv_h[DD * KK], g_wv_l[DD * KK];
__device__ __nv_bfloat16 g_wo_h[DD * KK], g_wo_l[DD * KK];
__device__ __nv_bfloat16 g_q_h[CH], g_q_l[CH];     // [B,H,T,HD]
__device__ __nv_bfloat16 g_k_h[CH], g_k_l[CH];     // [B,H,S,HD]
__device__ __nv_bfloat16 g_v_h[CH], g_v_l[CH];     // [B,H,HD,S]  (transposed)
__device__ __nv_bfloat16 g_c_h[MM * DD], g_c_l[MM * DD];   // ctx [B,T,D]

// ---------------------------------------------------------------------------
// Helpers (baseline sm_80 features only)
// ---------------------------------------------------------------------------
__device__ __forceinline__ uint32_t smem_to_u32(const void* p) {
    uint32_t a;
    asm("{ .reg .u64 t; cvta.to.shared.u64 t, %1; cvt.u32.u64 %0, t; }" : "=r"(a) : "l"(p));
    return a;
}
__device__ __forceinline__ void cp_async16(uint32_t dst, const void* src) {
    asm volatile("cp.async.cg.shared.global [%0], [%1], 16;" :: "r"(dst), "l"(src));
}
#define CP_ASYNC_COMMIT() asm volatile("cp.async.commit_group;" ::: "memory")
#define CP_ASYNC_WAIT(n)  asm volatile("cp.async.wait_group %0;" :: "n"(n) : "memory")

__device__ __forceinline__ void ldm4(uint32_t* r, uint32_t addr) {
    asm volatile("ldmatrix.sync.aligned.m8n8.x4.shared.b16 {%0,%1,%2,%3}, [%4];"
                 : "=r"(r[0]), "=r"(r[1]), "=r"(r[2]), "=r"(r[3]) : "r"(addr));
}
__device__ __forceinline__ void mma16816(float* c, const uint32_t* a, uint32_t b0, uint32_t b1) {
    asm volatile("mma.sync.aligned.m16n8k16.row.col.f32.bf16.bf16.f32 "
                 "{%0,%1,%2,%3}, {%4,%5,%6,%7}, {%8,%9}, {%0,%1,%2,%3};"
                 : "+f"(c[0]), "+f"(c[1]), "+f"(c[2]), "+f"(c[3])
                 : "r"(a[0]), "r"(a[1]), "r"(a[2]), "r"(a[3]), "r"(b0), "r"(b1));
}
__device__ __forceinline__ uint32_t packbf(__nv_bfloat16 a, __nv_bfloat16 b) {
    __nv_bfloat162 t(a, b);
    return *reinterpret_cast<uint32_t*>(&t);
}
__device__ __forceinline__ void split_pack(float x, float y, uint32_t& hp, uint32_t& lp) {
    __nv_bfloat16 hx = __float2bfloat16(x), hy = __float2bfloat16(y);
    __nv_bfloat16 lx = __float2bfloat16(x - __bfloat162float(hx));
    __nv_bfloat16 ly = __float2bfloat16(y - __bfloat162float(hy));
    hp = packbf(hx, hy); lp = packbf(lx, ly);
}

// ---------------------------------------------------------------------------
// fp32 -> bf16 hi/lo split
// ---------------------------------------------------------------------------
__global__ void split_kernel(const float* __restrict__ x,
                             __nv_bfloat16* __restrict__ hi,
                             __nv_bfloat16* __restrict__ lo, int n4)
{
    int i = blockIdx.x * 256 + threadIdx.x;
    if (i >= n4) return;
    float4 v = ((const float4*)x)[i];
    uint32_t h0, l0, h1, l1;
    split_pack(v.x, v.y, h0, l0);
    split_pack(v.z, v.w, h1, l1);
    ((uint32_t*)hi)[2 * i]     = h0;
    ((uint32_t*)hi)[2 * i + 1] = h1;
    ((uint32_t*)lo)[2 * i]     = l0;
    ((uint32_t*)lo)[2 * i + 1] = l1;
}

// ---------------------------------------------------------------------------
// bf16x3 GEMM via mma.sync + ldmatrix: out[m,n] = sum_k A[m,k]*W[n,k]
// CTA tile 128x128, BK=32, 256 thr (8 warps, 4m x 2n), warp tile 32x64.
// smem tile: 128 rows x 80B (64B data + 16B pad), NO XOR (pad alone is
// conflict-free: 20r mod 32 is a permutation of bank groups).
// ---------------------------------------------------------------------------
#define TILE_B 10240
#define STAGE_B (4 * TILE_B)
#define SMEM_GEMM (2 * STAGE_B)
#define NSTAGES (KK / 32)

__device__ __forceinline__ void load_stage_g(
    uint32_t sbuf, int s, int m0, int n0,
    const __nv_bfloat16* __restrict__ Ah, const __nv_bfloat16* __restrict__ Al,
    const __nv_bfloat16* __restrict__ Wh, const __nv_bfloat16* __restrict__ Wl, int tid)
{
    const int k0 = s * 32;
    #pragma unroll
    for (int half = 0; half < 2; ++half) {
        const int id = tid + 256 * half;
        const int r = id >> 2, c = id & 3;
        const uint32_t doff = r * 80 + c * 16;
        const size_t gA = (size_t)(m0 + r) * KK + k0 + c * 8;
        const size_t gW = (size_t)(n0 + r) * KK + k0 + c * 8;
        cp_async16(sbuf + doff,              Ah + gA);
        cp_async16(sbuf + TILE_B + doff,     Al + gA);
        cp_async16(sbuf + 2 * TILE_B + doff, Wh + gW);
        cp_async16(sbuf + 3 * TILE_B + doff, Wl + gW);
    }
}

template<bool QKV>
__global__ __launch_bounds__(256, 1)
void gemm_kernel(const __nv_bfloat16* __restrict__ a0h, const __nv_bfloat16* __restrict__ a0l,
                 const __nv_bfloat16* __restrict__ a1h, const __nv_bfloat16* __restrict__ a1l,
                 const __nv_bfloat16* __restrict__ wqh, const __nv_bfloat16* __restrict__ wql,
                 const __nv_bfloat16* __restrict__ wkh, const __nv_bfloat16* __restrict__ wkl,
                 const __nv_bfloat16* __restrict__ wvh, const __nv_bfloat16* __restrict__ wvl,
                 const float* __restrict__ cq, const float* __restrict__ sq,
                 const float* __restrict__ ck, const float* __restrict__ sk,
                 __nv_bfloat16* __restrict__ qh, __nv_bfloat16* __restrict__ ql,
                 __nv_bfloat16* __restrict__ kh, __nv_bfloat16* __restrict__ kl,
                 __nv_bfloat16* __restrict__ vh, __nv_bfloat16* __restrict__ vl,
                 float* __restrict__ fout)
{
    extern __shared__ __align__(128) uint8_t smem_raw[];
    const uint32_t sbase = smem_to_u32(smem_raw);
    const int tid = threadIdx.x;
    const int m0 = blockIdx.y * 128;
    const int n0 = blockIdx.x * 128;
    const int z  = QKV ? blockIdx.z : 0;

    const __nv_bfloat16 *Ah, *Al, *Wh, *Wl;
    if (QKV) {
        Ah = (z == 0) ? a0h : a1h;
        Al = (z == 0) ? a0l : a1l;
        Wh = (z == 0) ? wqh : (z == 1) ? wkh : wvh;
        Wl = (z == 0) ? wql : (z == 1) ? wkl : wvl;
    } else {
        Ah = a0h; Al = a0l; Wh = wqh; Wl = wql;
    }

    const int wid = tid >> 5, lid = tid & 31;
    const int wm = wid >> 1, wn = wid & 1;
    const int g = lid >> 2, t = lid & 3;
    const int lrow = lid & 15;
    const int lcolb = (lid >> 4) * 16;

    float acc[2][8][4];
    #pragma unroll
    for (int mt = 0; mt < 2; ++mt)
        #pragma unroll
        for (int nt = 0; nt < 8; ++nt)
            #pragma unroll
            for (int q = 0; q < 4; ++q) acc[mt][nt][q] = 0.0f;

    load_stage_g(sbase, 0, m0, n0, Ah, Al, Wh, Wl, tid);
    CP_ASYNC_COMMIT();

    for (int s = 0; s < NSTAGES; ++s) {
        if (s + 1 < NSTAGES) {
            load_stage_g(sbase + ((s + 1) & 1) * STAGE_B, s + 1, m0, n0, Ah, Al, Wh, Wl, tid);
            CP_ASYNC_COMMIT();
            CP_ASYNC_WAIT(1);
        } else {
            CP_ASYNC_WAIT(0);
        }
        __syncthreads();

        const uint32_t buf = sbase + (s & 1) * STAGE_B;
        const uint32_t aH = buf, aL = buf + TILE_B;
        const uint32_t bH = buf + 2 * TILE_B, bL = buf + 3 * TILE_B;

        #pragma unroll
        for (int kc = 0; kc < 2; ++kc) {
            const uint32_t cb = kc * 32 + lcolb;
            uint32_t ahf[2][4], alf[2][4];
            #pragma unroll
            for (int mt = 0; mt < 2; ++mt) {
                const uint32_t ro = (wm * 32 + mt * 16 + lrow) * 80 + cb;
                ldm4(ahf[mt], aH + ro);
                ldm4(alf[mt], aL + ro);
            }
            #pragma unroll
            for (int jp = 0; jp < 4; ++jp) {
                const uint32_t ro = (wn * 64 + jp * 16 + lrow) * 80 + cb;
                uint32_t bhf[4], blf[4];
                ldm4(bhf, bH + ro);
                ldm4(blf, bL + ro);
                #pragma unroll
                for (int mt = 0; mt < 2; ++mt) {
                    float* cA = acc[mt][2 * jp];
                    float* cB = acc[mt][2 * jp + 1];
                    mma16816(cA, ahf[mt], bhf[0], bhf[2]);
                    mma16816(cB, ahf[mt], bhf[1], bhf[3]);
                    mma16816(cA, alf[mt], bhf[0], bhf[2]);
                    mma16816(cB, alf[mt], bhf[1], bhf[3]);
                    mma16816(cA, ahf[mt], blf[0], blf[2]);
                    mma16816(cB, ahf[mt], blf[1], blf[3]);
                }
            }
        }
        __syncthreads();
    }

    // ---------------- epilogue ----------------
    #pragma unroll
    for (int mt = 0; mt < 2; ++mt) {
        #pragma unroll
        for (int rh = 0; rh < 2; ++rh) {
            const int m = m0 + wm * 32 + mt * 16 + g + rh * 8;
            const int tI = m & (TT - 1);
            const int b  = m >> 11;
            #pragma unroll
            for (int nt = 0; nt < 8; ++nt) {
                const int col = wn * 64 + nt * 8 + 2 * t;
                float v0 = acc[mt][nt][rh * 2 + 0];
                float v1 = acc[mt][nt][rh * 2 + 1];
                if (QKV) {
                    if (z < 2) {
                        const float* cT = (z == 0) ? cq : ck;
                        const float* sT = (z == 0) ? sq : sk;
                        const int d2 = col >> 1;
                        const float cs = cT[tI * 64 + d2];
                        const float sn = sT[tI * 64 + d2];
                        const float x0 = v0, x1 = v1;
                        v0 = x0 * cs - x1 * sn;
                        v1 = x1 * cs + x0 * sn;
                    }
                    const int hhead = blockIdx.x;
                    const size_t bh = (size_t)b * HH + hhead;
                    __nv_bfloat16 h0 = __float2bfloat16(v0), h1 = __float2bfloat16(v1);
                    __nv_bfloat16 e0 = __float2bfloat16(v0 - __bfloat162float(h0));
                    __nv_bfloat16 e1 = __float2bfloat16(v1 - __bfloat162float(h1));
                    if (z == 2) {
                        const size_t base = (bh * HD + col) * TT + tI;
                        vh[base] = h0; vh[base + TT] = h1;
                        vl[base] = e0; vl[base + TT] = e1;
                    } else {
                        const size_t off = (bh * TT + tI) * HD + col;
                        __nv_bfloat16* oh = (z == 0) ? qh : kh;
                        __nv_bfloat16* ol = (z == 0) ? ql : kl;
                        *(uint32_t*)(oh + off) = packbf(h0, h1);
                        *(uint32_t*)(ol + off) = packbf(e0, e1);
                    }
                } else {
                    float* op = fout + (size_t)m * DD + n0 + col;
                    *(float2*)op = make_float2(v0, v1);
                }
            }
        }
    }
}

// ---------------------------------------------------------------------------
// Flash attention, mma.sync bf16x3.
// Per CTA: one (b,h), 128 q rows; chunks of 64 kv. 8 warps x 16 rows.
// smem: Qh/Ql 128x272B; per buf: Kh/Kl 64x272B, Vh/Vl 128x144B. Dbl-buffered.
// ---------------------------------------------------------------------------
#define AQ_STR 272
#define AV_STR 144
#define OFF_QL 34816                 // 128*272
#define OFF_KV 69632
#define KV_BUF 71680                 // 2*17408 + 2*18432
#define OFF_KL 17408
#define OFF_VH 34816
#define OFF_VL 53248
#define ATT_SMEM (OFF_KV + 2 * KV_BUF)   // 212992

__device__ __forceinline__ void load_kv_chunk(
    uint32_t sb, int buf, int chunk, int bh,
    const __nv_bfloat16* __restrict__ kh_g, const __nv_bfloat16* __restrict__ kl_g,
    const __nv_bfloat16* __restrict__ vh_g, const __nv_bfloat16* __restrict__ vl_g, int tid)
{
    const uint32_t kb = sb + OFF_KV + buf * KV_BUF;
    const int s0 = chunk * 64;
    #pragma unroll
    for (int i = 0; i < 4; ++i) {
        const int idx = tid + 256 * i;          // 0..1023
        const int r = idx >> 4, c2 = idx & 15;  // K: 64 rows x 16 chunks
        const size_t gk = ((size_t)bh * TT + s0 + r) * HD + c2 * 8;
        cp_async16(kb + r * AQ_STR + c2 * 16,          kh_g + gk);
        cp_async16(kb + OFF_KL + r * AQ_STR + c2 * 16, kl_g + gk);
        const int rv = idx >> 3, cv = idx & 7;  // Vt: 128 rows x 8 chunks
        const size_t gv = ((size_t)bh * HD + rv) * TT + s0 + cv * 8;
        cp_async16(kb + OFF_VH + rv * AV_STR + cv * 16, vh_g + gv);
        cp_async16(kb + OFF_VL + rv * AV_STR + cv * 16, vl_g + gv);
    }
}

__global__ __launch_bounds__(256, 1)
void attn_kernel(const __nv_bfloat16* __restrict__ qh_g, const __nv_bfloat16* __restrict__ ql_g,
                 const __nv_bfloat16* __restrict__ kh_g, const __nv_bfloat16* __restrict__ kl_g,
                 const __nv_bfloat16* __restrict__ vh_g, const __nv_bfloat16* __restrict__ vl_g,
                 __nv_bfloat16* __restrict__ ch_g, __nv_bfloat16* __restrict__ cl_g)
{
    extern __shared__ __align__(128) uint8_t sm_raw[];
    const uint32_t sb = smem_to_u32(sm_raw);
    const int tid = threadIdx.x;
    const int wid = tid >> 5, lid = tid & 31;
    const int g = lid >> 2, t = lid & 3;
    const int bh = blockIdx.y;
    const int b = bh >> 4, h = bh & 15;
    const int q0 = blockIdx.x * 128;
    const int lrow = lid & 15;
    const int lcolb = (lid >> 4) * 16;

    // Q tile (hi/lo) loads
    const size_t qoff = ((size_t)bh * TT + q0) * HD;
    #pragma unroll
    for (int i = 0; i < 8; ++i) {
        const int idx = tid + 256 * i;          // 0..2047
        const int r = idx >> 4, c2 = idx & 15;
        const size_t gq = qoff + (size_t)r * HD + c2 * 8;
        cp_async16(sb + r * AQ_STR + c2 * 16,          qh_g + gq);
        cp_async16(sb + OFF_QL + r * AQ_STR + c2 * 16, ql_g + gq);
    }
    load_kv_chunk(sb, 0, 0, bh, kh_g, kl_g, vh_g, vl_g, tid);
    CP_ASYNC_COMMIT();
    load_kv_chunk(sb, 1, 1, bh, kh_g, kl_g, vh_g, vl_g, tid);
    CP_ASYNC_COMMIT();

    float O[16][4];
    #pragma unroll
    for (int nv = 0; nv < 16; ++nv)
        #pragma unroll
        for (int q = 0; q < 4; ++q) O[nv][q] = 0.0f;
    float mr0 = -1e30f, mr1 = -1e30f, lr0 = 0.0f, lr1 = 0.0f;

    for (int c = 0; c < 32; ++c) {
        CP_ASYNC_WAIT(1);
        __syncthreads();
        const uint32_t kb = sb + OFF_KV + (c & 1) * KV_BUF;

        // ---- S = Q K^T (bf16x3) ----
        float S[8][4];
        #pragma unroll
        for (int j = 0; j < 8; ++j)
            #pragma unroll
            for (int q = 0; q < 4; ++q) S[j][q] = 0.0f;

        #pragma unroll
        for (int ks = 0; ks < 8; ++ks) {
            const uint32_t cb = ks * 32 + lcolb;
            uint32_t qhf[4], qlf[4];
            const uint32_t qo = (wid * 16 + lrow) * AQ_STR + cb;
            ldm4(qhf, sb + qo);
            ldm4(qlf, sb + OFF_QL + qo);
            #pragma unroll
            for (int jp = 0; jp < 4; ++jp) {
                const uint32_t ro = (jp * 16 + lrow) * AQ_STR + cb;
                uint32_t bhf[4], blf[4];
                ldm4(bhf, kb + ro);
                ldm4(blf, kb + OFF_KL + ro);
                float* cA = S[2 * jp];
                float* cB = S[2 * jp + 1];
                mma16816(cA, qhf, bhf[0], bhf[2]);
                mma16816(cB, qhf, bhf[1], bhf[3]);
                mma16816(cA, qlf, bhf[0], bhf[2]);
                mma16816(cB, qlf, bhf[1], bhf[3]);
                mma16816(cA, qhf, blf[0], blf[2]);
                mma16816(cB, qhf, blf[1], blf[3]);
            }
        }

        // ---- online softmax (rows g and g+8, per-thread 16 cols each) ----
        float mx0 = -1e30f, mx1 = -1e30f;
        #pragma unroll
        for (int j = 0; j < 8; ++j) {
            #pragma unroll
            for (int q = 0; q < 4; ++q) S[j][q] *= SCALE;
            mx0 = fmaxf(mx0, fmaxf(S[j][0], S[j][1]));
            mx1 = fmaxf(mx1, fmaxf(S[j][2], S[j][3]));
        }
        mx0 = fmaxf(mx0, __shfl_xor_sync(0xffffffffu, mx0, 1));
        mx0 = fmaxf(mx0, __shfl_xor_sync(0xffffffffu, mx0, 2));
        mx1 = fmaxf(mx1, __shfl_xor_sync(0xffffffffu, mx1, 1));
        mx1 = fmaxf(mx1, __shfl_xor_sync(0xffffffffu, mx1, 2));
        const float mn0 = fmaxf(mr0, mx0), mn1 = fmaxf(mr1, mx1);
        const float cr0 = __expf(mr0 - mn0), cr1 = __expf(mr1 - mn1);
        mr0 = mn0; mr1 = mn1;
        float ls0 = 0.0f, ls1 = 0.0f;
        #pragma unroll
        for (int j = 0; j < 8; ++j) {
            S[j][0] = __expf(S[j][0] - mn0);
            S[j][1] = __expf(S[j][1] - mn0);
            S[j][2] = __expf(S[j][2] - mn1);
            S[j][3] = __expf(S[j][3] - mn1);
            ls0 += S[j][0] + S[j][1];
            ls1 += S[j][2] + S[j][3];
        }
        ls0 += __shfl_xor_sync(0xffffffffu, ls0, 1);
        ls0 += __shfl_xor_sync(0xffffffffu, ls0, 2);
        ls1 += __shfl_xor_sync(0xffffffffu, ls1, 1);
        ls1 += __shfl_xor_sync(0xffffffffu, ls1, 2);
        lr0 = lr0 * cr0 + ls0;
        lr1 = lr1 * cr1 + ls1;
        #pragma unroll
        for (int nv = 0; nv < 16; ++nv) {
            O[nv][0] *= cr0; O[nv][1] *= cr0;
            O[nv][2] *= cr1; O[nv][3] *= cr1;
        }

        // ---- P fragments (registers only) ----
        uint32_t ph[4][4], pl[4][4];
        #pragma unroll
        for (int kk = 0; kk < 4; ++kk) {
            split_pack(S[2 * kk][0],     S[2 * kk][1],     ph[kk][0], pl[kk][0]);
            split_pack(S[2 * kk][2],     S[2 * kk][3],     ph[kk][1], pl[kk][1]);
            split_pack(S[2 * kk + 1][0], S[2 * kk + 1][1], ph[kk][2], pl[kk][2]);
            split_pack(S[2 * kk + 1][2], S[2 * kk + 1][3], ph[kk][3], pl[kk][3]);
        }

        // ---- O += P V (bf16x3) ----
        const uint32_t vbh = kb + OFF_VH, vbl = kb + OFF_VL;
        #pragma unroll
        for (int kk = 0; kk < 4; ++kk) {
            const uint32_t cb = kk * 32 + lcolb;
            #pragma unroll
            for (int np = 0; np < 8; ++np) {
                const uint32_t ro = (np * 16 + lrow) * AV_STR + cb;
                uint32_t vhf[4], vlf[4];
                ldm4(vhf, vbh + ro);
                ldm4(vlf, vbl + ro);
                float* cA = O[2 * np];
                float* cB = O[2 * np + 1];
                mma16816(cA, ph[kk], vhf[0], vhf[2]);
                mma16816(cB, ph[kk], vhf[1], vhf[3]);
                mma16816(cA, pl[kk], vhf[0], vhf[2]);
                mma16816(cB, pl[kk], vhf[1], vhf[3]);
                mma16816(cA, ph[kk], vlf[0], vlf[2]);
                mma16816(cB, ph[kk], vlf[1], vlf[3]);
            }
        }

        __syncthreads();
        if (c + 2 < 32)
            load_kv_chunk(sb, c & 1, c + 2, bh, kh_g, kl_g, vh_g, vl_g, tid);
        CP_ASYNC_COMMIT();
    }

    // ---- epilogue: ctx[b][t][h*128 + d] as bf16 hi/lo ----
    const float inv0 = 1.0f / lr0, inv1 = 1.0f / lr1;
    const int t0 = q0 + wid * 16 + g;
    const int t1 = t0 + 8;
    #pragma unroll
    for (int nv = 0; nv < 16; ++nv) {
        const int d = h * HD + nv * 8 + 2 * t;
        const size_t o0 = ((size_t)b * TT + t0) * DD + d;
        const size_t o1 = ((size_t)b * TT + t1) * DD + d;
        uint32_t hp, lp;
        split_pack(O[nv][0] * inv0, O[nv][1] * inv0, hp, lp);
        *(uint32_t*)(ch_g + o0) = hp;
        *(uint32_t*)(cl_g + o0) = lp;
        split_pack(O[nv][2] * inv1, O[nv][3] * inv1, hp, lp);
        *(uint32_t*)(ch_g + o1) = hp;
        *(uint32_t*)(cl_g + o1) = lp;
    }
}

// ---------------------------------------------------------------------------
extern "C" void kernel_launch(void* const* d_in, const int* in_sizes, int n_in,
                              void* d_out, int out_size)
{
    const float* hs  = (const float*)d_in[0];
    const float* enc = (const float*)d_in[1];
    const float* Wq  = (const float*)d_in[2];
    const float* Wk  = (const float*)d_in[3];
    const float* Wv  = (const float*)d_in[4];
    const float* Wo  = (const float*)d_in[5];
    const float* cq  = (const float*)d_in[6];
    const float* sq  = (const float*)d_in[7];
    const float* ck  = (const float*)d_in[8];
    const float* sk  = (const float*)d_in[9];

    __nv_bfloat16 *hs_h, *hs_l, *enc_h, *enc_l;
    __nv_bfloat16 *wq_h, *wq_l, *wk_h, *wk_l, *wv_h, *wv_l, *wo_h, *wo_l;
    __nv_bfloat16 *q_h, *q_l, *k_h, *k_l, *v_h, *v_l, *c_h, *c_l;
    cudaGetSymbolAddress((void**)&hs_h,  g_hs_h);  cudaGetSymbolAddress((void**)&hs_l,  g_hs_l);
    cudaGetSymbolAddress((void**)&enc_h, g_enc_h); cudaGetSymbolAddress((void**)&enc_l, g_enc_l);
    cudaGetSymbolAddress((void**)&wq_h,  g_wq_h);  cudaGetSymbolAddress((void**)&wq_l,  g_wq_l);
    cudaGetSymbolAddress((void**)&wk_h,  g_wk_h);  cudaGetSymbolAddress((void**)&wk_l,  g_wk_l);
    cudaGetSymbolAddress((void**)&wv_h,  g_wv_h);  cudaGetSymbolAddress((void**)&wv_l,  g_wv_l);
    cudaGetSymbolAddress((void**)&wo_h,  g_wo_h);  cudaGetSymbolAddress((void**)&wo_l,  g_wo_l);
    cudaGetSymbolAddress((void**)&q_h, g_q_h); cudaGetSymbolAddress((void**)&q_l, g_q_l);
    cudaGetSymbolAddress((void**)&k_h, g_k_h); cudaGetSymbolAddress((void**)&k_l, g_k_l);
    cudaGetSymbolAddress((void**)&v_h, g_v_h); cudaGetSymbolAddress((void**)&v_l, g_v_l);
    cudaGetSymbolAddress((void**)&c_h, g_c_h); cudaGetSymbolAddress((void**)&c_l, g_c_l);

    const int nA4 = MM * KK / 4, nW4 = DD * KK / 4;
    split_kernel<<<(nA4 + 255) / 256, 256>>>(hs,  hs_h,  hs_l,  nA4);
    split_kernel<<<(nA4 + 255) / 256, 256>>>(enc, enc_h, enc_l, nA4);
    split_kernel<<<(nW4 + 255) / 256, 256>>>(Wq,  wq_h,  wq_l,  nW4);
    split_kernel<<<(nW4 + 255) / 256, 256>>>(Wk,  wk_h,  wk_l,  nW4);
    split_kernel<<<(nW4 + 255) / 256, 256>>>(Wv,  wv_h,  wv_l,  nW4);
    split_kernel<<<(nW4 + 255) / 256, 256>>>(Wo,  wo_h,  wo_l,  nW4);

    cudaFuncSetAttribute(gemm_kernel<true>,
                         cudaFuncAttributeMaxDynamicSharedMemorySize, SMEM_GEMM);
    cudaFuncSetAttribute(gemm_kernel<false>,
                         cudaFuncAttributeMaxDynamicSharedMemorySize, SMEM_GEMM);
    cudaFuncSetAttribute(attn_kernel,
                         cudaFuncAttributeMaxDynamicSharedMemorySize, ATT_SMEM);

    // Q/K/V projections (+RoPE, +head split, +V transpose, bf16 h/l outputs)
    gemm_kernel<true><<<dim3(DD / 128, MM / 128, 3), 256, SMEM_GEMM>>>(
        hs_h, hs_l, enc_h, enc_l, wq_h, wq_l, wk_h, wk_l, wv_h, wv_l,
        cq, sq, ck, sk, q_h, q_l, k_h, k_l, v_h, v_l, nullptr);

    // Attention
    attn_kernel<<<dim3(TT / 128, BB * HH), 256, ATT_SMEM>>>(
        q_h, q_l, k_h, k_l, v_h, v_l, c_h, c_l);

    // Output projection (fp32 out)
    gemm_kernel<false><<<dim3(DD / 128, MM / 128, 1), 256, SMEM_GEMM>>>(
        c_h, c_l, nullptr, nullptr, wo_h, wo_l, nullptr, nullptr, nullptr, nullptr,
        nullptr, nullptr, nullptr, nullptr,
        nullptr, nullptr, nullptr, nullptr, nullptr, nullptr, (float*)d_out);
}